// round 17
// baseline (speedup 1.0000x reference)
#include <cuda_runtime.h>
#include <cuda_fp16.h>
#include <stdint.h>
#include <math.h>

#define B_    128
#define N_    196
#define ENC_  2048
#define DEC_  512
#define ATT_  512
#define M_    (B_ * N_)          // 25088 rows
#define ENCH_ (ENC_ / 2)         // u32 (fp16x2) per enc row
#define KF_TOT (ENC_ / 16)       // 128 k16 fragments
#define FNP_TOT (ATT_ / 16)      // 32 fn-pairs

// gemm tiling: block 128m x 128n x 64k, 256 thr (4M x 2N warps), 3-stage, 2 CTA/SM
// stage: A fp16 128x64 swizzled (16KB) + B fp16 paired frag (16KB) = 32KB
#define NKS        32            // k-steps of 64
#define STAGE_U32  8192          // 32KB per stage
#define NSTG       3
#define SMEM_BYTES (NSTG * STAGE_U32 * 4)   // 98304 (x2 CTA = 192KB)

// ---- scratch (__device__ globals: sanctioned no-alloc workaround) ----
__device__ float    g_att2[B_ * ATT_];
__device__ float    g_epart[M_ * 4];
__device__ uint32_t g_ench[(size_t)M_ * ENCH_];     // enc fp16 row-major (102MB)
__device__ uint32_t g_Bf2[FNP_TOT * KF_TOT * 128];  // B fp16 pair-frag, permuted k

// ============================================================
// helpers
// ============================================================
__device__ __forceinline__ uint32_t pack_h2(__half lo, __half hi) {
    __half2 p; p.x = lo; p.y = hi;       // .x = low 16 bits (lower k index)
    return *reinterpret_cast<uint32_t*>(&p);
}
__device__ __forceinline__ void cp16(uint32_t saddr, const void* g) {
    asm volatile("cp.async.cg.shared.global [%0], [%1], 16;\n" :: "r"(saddr), "l"(g));
}
__device__ __forceinline__ void cp_commit() { asm volatile("cp.async.commit_group;\n"); }
template <int NN> __device__ __forceinline__ void cp_wait() {
    asm volatile("cp.async.wait_group %0;\n" :: "n"(NN));
}
__device__ __forceinline__ void mma16816(float c[4], const uint32_t a[4], const uint32_t b[2]) {
    asm volatile(
        "mma.sync.aligned.m16n8k16.row.col.f32.f16.f16.f32 "
        "{%0,%1,%2,%3}, {%4,%5,%6,%7}, {%8,%9}, {%0,%1,%2,%3};\n"
        : "+f"(c[0]), "+f"(c[1]), "+f"(c[2]), "+f"(c[3])
        : "r"(a[0]), "r"(a[1]), "r"(a[2]), "r"(a[3]),
          "r"(b[0]), "r"(b[1]));
}

// ============================================================
// Kernel 0: prepackA_row — enc fp32 -> fp16x2 row-major (coalesced)
// ============================================================
__global__ void prepackA_row(const float* __restrict__ enc) {
    size_t idx = (size_t)blockIdx.x * 256 + threadIdx.x;
    float2 v = reinterpret_cast<const float2*>(enc)[idx];
    g_ench[idx] = pack_h2(__float2half_rn(v.x), __float2half_rn(v.y));
}

// ============================================================
// Kernel 1: att2 = decoder_hidden @ W_dec + b_dec   (R14 form, exact)
// ============================================================
__global__ __launch_bounds__(512)
void att2_kernel(const float* __restrict__ dec,
                 const float* __restrict__ Wdec,
                 const float* __restrict__ bdec) {
    __shared__ float ds[16][DEC_];
    const int tid = threadIdx.x;
    const int ax  = blockIdx.x & 15;
    const int bgp = blockIdx.x >> 4;
    const int a  = ax * 32 + (tid & 31);
    const int bl = tid >> 5;
    const int b  = bgp * 16 + bl;

#pragma unroll
    for (int j = 0; j < 4; j++) {
        int lin = j * 512 + tid;
        int row = lin >> 7;
        int c4  = lin & 127;
        *reinterpret_cast<float4*>(&ds[row][c4 * 4]) =
            *reinterpret_cast<const float4*>(&dec[(size_t)(bgp * 16 + row) * DEC_ + c4 * 4]);
    }
    __syncthreads();

    float a0 = 0.f, a1 = 0.f, a2 = 0.f, a3 = 0.f;
#pragma unroll 4
    for (int d = 0; d < DEC_; d += 4) {
        float w0 = Wdec[(size_t)(d + 0) * ATT_ + a];
        float w1 = Wdec[(size_t)(d + 1) * ATT_ + a];
        float w2 = Wdec[(size_t)(d + 2) * ATT_ + a];
        float w3 = Wdec[(size_t)(d + 3) * ATT_ + a];
        a0 += ds[bl][d + 0] * w0;
        a1 += ds[bl][d + 1] * w1;
        a2 += ds[bl][d + 2] * w2;
        a3 += ds[bl][d + 3] * w3;
    }
    g_att2[(size_t)b * ATT_ + a] = ((a0 + a1) + (a2 + a3)) + bdec[a];
}

// ============================================================
// Prepack B: W_enc [K][N] -> fp16 PAIRED frag layout, permuted k
//   layout [fnp][kf][lane][rr4]; rr = fn_sub*2 + kreg
//   n = fnp*16 + fn_sub*8 + (lane>>2)
//   k = kf*16 + (lane&3)*4 + kreg*2   (A uses same permutation)
// ============================================================
__global__ void prepackB(const float* __restrict__ Wenc) {
    int idx = blockIdx.x * 256 + threadIdx.x;
    int rr   = idx & 3;
    int lane = (idx >> 2) & 31;
    int kf   = (idx >> 7) & (KF_TOT - 1);
    int fnp  = idx >> 14;
    int n = fnp * 16 + (rr >> 1) * 8 + (lane >> 2);
    int k = kf * 16 + (lane & 3) * 4 + (rr & 1) * 2;
    float v0 = Wenc[(size_t)k * ATT_ + n];
    float v1 = Wenc[(size_t)(k + 1) * ATT_ + n];
    g_Bf2[idx] = pack_h2(__float2half_rn(v0), __float2half_rn(v1));
}

// ============================================================
// Kernel 2: HMMA GEMM (1-term fp16, A pre-packed fp16) + fused epilogue
//   block 128m x 128n x 64k; 8 warps (4M x 2N), warp tile 32x64
//   A smem: 128 rows x 16 8B-units, swizzle su = (u + row*4) & 15
//   grid (nchunk=4 fastest, mtile=196); 3-stage, 2 CTAs/SM
// ============================================================
__global__ __launch_bounds__(256, 2)
void gemm_e_kernel(const float* __restrict__ benc,
                   const float* __restrict__ Wfull) {
    extern __shared__ uint32_t sm[];   // 3 stages x 8192 u32
    const int tid = threadIdx.x;
    const int lane = tid & 31, wid = tid >> 5;
    const int warpM = wid & 3, warpN = wid >> 2;   // 4M x 2N
    const int nchunk = blockIdx.x;     // 0..3
    const int mtile  = blockIdx.y;     // 0..195
    const int m0g = mtile * 128;
    const int g = lane >> 2, tig = lane & 3;

    const uint32_t smbase = (uint32_t)__cvta_generic_to_shared(sm);

    float acc[2][8][4];
#pragma unroll
    for (int i = 0; i < 2; i++)
#pragma unroll
        for (int j = 0; j < 8; j++)
#pragma unroll
            for (int q = 0; q < 4; q++) acc[i][j][q] = 0.f;

    // ---- async load of k-step ks (64 k): A fp16 + B fp16; 8/thread ----
    auto issue = [&](int ks, int st) {
        const uint32_t so = smbase + (uint32_t)(st * STAGE_U32) * 4u;
#pragma unroll
        for (int i = 0; i < 8; i++) {
            int c = i * 256 + tid;           // 0..2047
            uint32_t dst;
            const void* src;
            if (c < 1024) {                  // A: row(128) x chunk(8) of 16B
                int row = c >> 3, cc = c & 7;
                int su = (2 * cc + row * 4) & 15;       // 8B-unit swizzle
                src = g_ench + (size_t)(m0g + row) * ENCH_ + ks * 32 + cc * 4;
                dst = so + (uint32_t)(row * 32 + su * 2) * 4u;
            } else {                         // B paired: fnp8 kf4 ln32
                int d = c - 1024;
                int fnp = d >> 7, kf = (d >> 5) & 3, ln = d & 31;
                src = g_Bf2 + ((size_t)(nchunk * 8 + fnp) * KF_TOT + (ks * 4 + kf)) * 128 + ln * 4;
                dst = so + (uint32_t)(4096 + (fnp * 4 + kf) * 128 + ln * 4) * 4u;
            }
            cp16(dst, src);
        }
        cp_commit();
    };

    issue(0, 0);
    issue(1, 1);

    for (int s = 0; s < NKS; s++) {
        const int st = s % NSTG;
        if (s + 1 < NKS) cp_wait<1>(); else cp_wait<0>();
        __syncthreads();
        if (s + 2 < NKS) issue(s + 2, (s + 2) % NSTG);

        const int sb = st * STAGE_U32;
#pragma unroll
        for (int kf = 0; kf < 4; kf++) {
            const int u = kf * 4 + tig;      // 8B-unit index within row
            // A fragments: 2x LDS.64 per fm (no cvt)
            uint32_t a[2][4];
#pragma unroll
            for (int fm = 0; fm < 2; fm++) {
                int rbase = (warpM * 2 + fm) * 16;
                int r0 = rbase + g, r1 = rbase + 8 + g;
                uint2 va = *reinterpret_cast<const uint2*>(
                    &sm[sb + r0 * 32 + ((u + r0 * 4) & 15) * 2]);
                uint2 vb = *reinterpret_cast<const uint2*>(
                    &sm[sb + r1 * 32 + ((u + r1 * 4) & 15) * 2]);
                a[fm][0] = va.x; a[fm][2] = va.y;
                a[fm][1] = vb.x; a[fm][3] = vb.y;
            }
            // B fragments: 4x LDS.128 (paired fn)
            uint32_t b[8][2];
#pragma unroll
            for (int fnp = 0; fnp < 4; fnp++) {
                int fnpAbs = warpN * 4 + fnp;
                uint4 v = *reinterpret_cast<const uint4*>(
                    &sm[sb + 4096 + (fnpAbs * 4 + kf) * 128 + lane * 4]);
                b[fnp * 2][0] = v.x;      b[fnp * 2][1] = v.y;
                b[fnp * 2 + 1][0] = v.z;  b[fnp * 2 + 1][1] = v.w;
            }
#pragma unroll
            for (int fm = 0; fm < 2; fm++)
#pragma unroll
                for (int fn = 0; fn < 8; fn++)
                    mma16816(acc[fm][fn], a[fm], b[fn]);
        }
    }

    // ---- fused epilogue: v = relu(acc + b_enc + att2); e += v * W_full ----
    float ep[2][2] = {{0.f, 0.f}, {0.f, 0.f}};
#pragma unroll
    for (int fm = 0; fm < 2; fm++) {
        int r0 = warpM * 32 + fm * 16 + g;
        int b0 = (m0g + r0) / N_;
        int b1 = (m0g + r0 + 8) / N_;
#pragma unroll
        for (int fn = 0; fn < 8; fn++) {
            int a0i = nchunk * 128 + warpN * 64 + fn * 8 + tig * 2;
            int a1i = a0i + 1;
            float w0 = Wfull[a0i], w1 = Wfull[a1i];
            float be0 = benc[a0i], be1 = benc[a1i];
            float t00 = g_att2[b0 * ATT_ + a0i];
            float t01 = g_att2[b0 * ATT_ + a1i];
            float t10 = g_att2[b1 * ATT_ + a0i];
            float t11 = g_att2[b1 * ATT_ + a1i];
            ep[fm][0] += fmaxf(acc[fm][fn][0] + be0 + t00, 0.f) * w0;
            ep[fm][0] += fmaxf(acc[fm][fn][1] + be1 + t01, 0.f) * w1;
            ep[fm][1] += fmaxf(acc[fm][fn][2] + be0 + t10, 0.f) * w0;
            ep[fm][1] += fmaxf(acc[fm][fn][3] + be1 + t11, 0.f) * w1;
        }
    }
#pragma unroll
    for (int off = 1; off <= 2; off <<= 1)
#pragma unroll
        for (int fm = 0; fm < 2; fm++) {
            ep[fm][0] += __shfl_xor_sync(0xffffffffu, ep[fm][0], off);
            ep[fm][1] += __shfl_xor_sync(0xffffffffu, ep[fm][1], off);
        }

    __syncthreads();
    float* e_red = reinterpret_cast<float*>(sm);  // [128][2]
    if (tig == 0) {
#pragma unroll
        for (int fm = 0; fm < 2; fm++) {
            int r0 = warpM * 32 + fm * 16 + g;
            e_red[r0 * 2 + warpN]       = ep[fm][0];
            e_red[(r0 + 8) * 2 + warpN] = ep[fm][1];
        }
    }
    __syncthreads();
    if (tid < 128)
        g_epart[(size_t)(m0g + tid) * 4 + nchunk] = e_red[tid * 2] + e_red[tid * 2 + 1];
}

// ============================================================
// Kernel 3: fused softmax + awe — reads fp16 enc (half the bytes)
//   grid (2, B) x 256 threads; 7 accumulator chains
// ============================================================
__global__ void awe_kernel(const float* __restrict__ bfull_p,
                           float* __restrict__ out_alpha,
                           float* __restrict__ out_awe) {
    __shared__ float al[N_];
    __shared__ float red[256];
    int b = blockIdx.y, tid = threadIdx.x;
    float bfull = *bfull_p;

    // ---- softmax over n (196) ----
    float ev = -INFINITY;
    float sval = 0.f;
    if (tid < N_) {
        const float* p = &g_epart[(size_t)(b * N_ + tid) * 4];
        sval = bfull + p[0] + p[1] + p[2] + p[3];
        ev = sval;
    }
    red[tid] = ev; __syncthreads();
#pragma unroll
    for (int off = 128; off > 0; off >>= 1) {
        if (tid < off) red[tid] = fmaxf(red[tid], red[tid + off]);
        __syncthreads();
    }
    float mx = red[0]; __syncthreads();
    float ex = 0.f;
    if (tid < N_) ex = expf(sval - mx);
    red[tid] = ex; __syncthreads();
#pragma unroll
    for (int off = 128; off > 0; off >>= 1) {
        if (tid < off) red[tid] += red[tid + off];
        __syncthreads();
    }
    float inv = 1.f / red[0];
    if (tid < N_) {
        float a = ex * inv;
        al[tid] = a;
        if (blockIdx.x == 0) out_alpha[b * N_ + tid] = a;
    }
    __syncthreads();

    // ---- weighted encoding from fp16 enc: 4 floats/thread, 7 chains ----
    int e0 = (blockIdx.x * 256 + tid) * 4;            // float index
    const uint2* p = reinterpret_cast<const uint2*>(
        g_ench + (size_t)b * N_ * ENCH_ + (e0 >> 1)); // 2 u32 = 4 fp16
    float4 acc[7];
#pragma unroll
    for (int c = 0; c < 7; c++) acc[c] = make_float4(0.f, 0.f, 0.f, 0.f);

#pragma unroll 4
    for (int n = 0; n < 28; n++) {
#pragma unroll
        for (int c = 0; c < 7; c++) {
            uint2 raw = p[(size_t)(n + c * 28) * (ENCH_ / 2)];
            __half2 h0 = *reinterpret_cast<__half2*>(&raw.x);
            __half2 h1 = *reinterpret_cast<__half2*>(&raw.y);
            float2 f0 = __half22float2(h0);
            float2 f1 = __half22float2(h1);
            float w = al[n + c * 28];
            acc[c].x += w * f0.x; acc[c].y += w * f0.y;
            acc[c].z += w * f1.x; acc[c].w += w * f1.y;
        }
    }
    float4 r;
    r.x = ((acc[0].x + acc[1].x) + (acc[2].x + acc[3].x)) + ((acc[4].x + acc[5].x) + acc[6].x);
    r.y = ((acc[0].y + acc[1].y) + (acc[2].y + acc[3].y)) + ((acc[4].y + acc[5].y) + acc[6].y);
    r.z = ((acc[0].z + acc[1].z) + (acc[2].z + acc[3].z)) + ((acc[4].z + acc[5].z) + acc[6].z);
    r.w = ((acc[0].w + acc[1].w) + (acc[2].w + acc[3].w)) + ((acc[4].w + acc[5].w) + acc[6].w);
    *reinterpret_cast<float4*>(out_awe + (size_t)b * ENC_ + e0) = r;
}

// ============================================================
extern "C" void kernel_launch(void* const* d_in, const int* in_sizes, int n_in,
                              void* d_out, int out_size) {
    const float* enc   = (const float*)d_in[0];
    const float* dech  = (const float*)d_in[1];
    const float* Wenc  = (const float*)d_in[2];
    const float* benc  = (const float*)d_in[3];
    const float* Wdec  = (const float*)d_in[4];
    const float* bdec  = (const float*)d_in[5];
    const float* Wfull = (const float*)d_in[6];
    const float* bfull = (const float*)d_in[7];

    float* out       = (float*)d_out;
    float* out_awe   = out;
    float* out_alpha = out + (size_t)B_ * ENC_;

    cudaFuncSetAttribute(gemm_e_kernel,
                         cudaFuncAttributeMaxDynamicSharedMemorySize, SMEM_BYTES);

    prepackA_row<<<(int)(((size_t)M_ * ENCH_) / 256), 256>>>(enc);
    att2_kernel<<<128, 512>>>(dech, Wdec, bdec);
    prepackB<<<FNP_TOT * KF_TOT * 128 / 256, 256>>>(Wenc);

    dim3 g2(4, 196);                           // nchunk fastest -> A L2 reuse
    gemm_e_kernel<<<g2, 256, SMEM_BYTES>>>(benc, Wfull);

    dim3 g3(2, B_);
    awe_kernel<<<g3, 256>>>(bfull, out_alpha, out_awe);
}